// round 15
// baseline (speedup 1.0000x reference)
#include <cuda_runtime.h>
#include <cuda_fp16.h>
#include <cstdint>

// Problem constants
#define BB   2
#define SS   2048
#define DIM  2048
#define NH   16
#define DH   128
#define LKV  512
#define LQ   1024
#define MR   (BB*SS)    // 4096
#define HD   (NH*DH)    // 2048

// fp32 scratch
__device__ float g_qr [MR*(size_t)HD];
__device__ float g_kr [MR*(size_t)HD];
__device__ float g_v  [MR*(size_t)HD];
__device__ float g_sc [(size_t)BB*NH*SS*SS];   // 512 MB scores

// plain fp16 operands
__device__ __half g_x   [MR*(size_t)DIM];
__device__ __half g_cq  [MR*(size_t)LQ];
__device__ __half g_ckv [MR*(size_t)LKV];
__device__ __half g_qa  [MR*(size_t)HD];
__device__ __half g_qrs [MR*(size_t)HD];
__device__ __half g_ka  [MR*(size_t)HD];
__device__ __half g_krs [MR*(size_t)HD];
__device__ __half g_vt  [(size_t)BB*NH*DH*SS];
__device__ __half g_p   [(size_t)BB*NH*SS*SS];
__device__ __half g_att [MR*(size_t)HD];
__device__ __half g_wlq [(size_t)LQ*DIM];
__device__ __half g_wlkv[(size_t)LKV*DIM];
__device__ __half g_wq  [(size_t)HD*LQ];
__device__ __half g_wqr [(size_t)HD*LQ];
__device__ __half g_wk  [(size_t)HD*LKV];
__device__ __half g_wv  [(size_t)HD*LKV];
__device__ __half g_wkr [(size_t)HD*DIM];
__device__ __half g_wo  [(size_t)DIM*HD];

// ---------------------------------------------------------------------------
// Helpers
// ---------------------------------------------------------------------------
__device__ __forceinline__ uint32_t smem_u32(const void* p) {
    uint32_t a;
    asm("{ .reg .u64 t; cvta.to.shared.u64 t, %1; cvt.u32.u64 %0, t; }" : "=r"(a) : "l"(p));
    return a;
}
__device__ __forceinline__ void ldm_x4(uint32_t addr, uint32_t r[4]) {
    asm volatile("ldmatrix.sync.aligned.m8n8.x4.shared.b16 {%0,%1,%2,%3}, [%4];"
                 : "=r"(r[0]), "=r"(r[1]), "=r"(r[2]), "=r"(r[3]) : "r"(addr));
}
__device__ __forceinline__ void mma_h(float c[4], const uint32_t a[4],
                                      uint32_t b0, uint32_t b1) {
    asm volatile(
        "mma.sync.aligned.m16n8k16.row.col.f32.f16.f16.f32 "
        "{%0,%1,%2,%3}, {%4,%5,%6,%7}, {%8,%9}, {%0,%1,%2,%3};"
        : "+f"(c[0]), "+f"(c[1]), "+f"(c[2]), "+f"(c[3])
        : "r"(a[0]), "r"(a[1]), "r"(a[2]), "r"(a[3]), "r"(b0), "r"(b1));
}
__device__ __forceinline__ uint32_t packh(float a, float b) {
    __half2 h = __floats2half2_rn(a, b);
    return *(uint32_t*)&h;
}

__device__ __forceinline__ void cp16(uint32_t dst, const void* src) {
    asm volatile("cp.async.cg.shared.global [%0], [%1], 16;" :: "r"(dst), "l"(src) : "memory");
}
#define CP_COMMIT asm volatile("cp.async.commit_group;" ::: "memory")
#define CP_WAIT0  asm volatile("cp.async.wait_group 0;" ::: "memory")
#define CP_WAIT1  asm volatile("cp.async.wait_group 1;" ::: "memory")

// SMEM per stage: A, B tiles [128 rows x 32 k fp16], pitch 80B
#define PITCH    80
#define OF_B     10240
#define STAGE_SZ 20480
#define NSTAGE   2
#define SMEMSZ   (NSTAGE*STAGE_SZ)     // 40960 -> 2 CTAs/SM easily

// Epilogue modes
#define OM_F32   0
#define OM_HALF  1

// ---------------------------------------------------------------------------
// bgemm: C = alpha * A * B^T [+ bias], plain fp16 operands, single MMA.
//   CTA tile 128x128, 256 threads = 8 warps (4M x 2N, warp 32x64).
//   DUAL: continue accumulating A2 * B2^T. OM: fp32 or fp16 output.
//   Batched via grid.z. Grid (N/128, M/128, Z). 2-stage cp.async pipeline.
// ---------------------------------------------------------------------------
template<int OM, bool BIAS, bool DUAL>
__global__ __launch_bounds__(256, 2)
void bgemm(int K,
           const __half* __restrict__ A, int lda, long long sAb, long long sAz,
           const __half* __restrict__ Bm, int ldb, long long sBb, long long sBz,
           const __half* __restrict__ A2, const __half* __restrict__ B2,
           float* __restrict__ C, int ldc, long long sCb, long long sCz,
           const float* __restrict__ bias, float alpha, int Hdiv,
           __half* __restrict__ Ch)
{
    extern __shared__ __align__(128) char smc[];
    const uint32_t smb = smem_u32(smc);
    const int tid  = threadIdx.x;
    const int lane = tid & 31;
    const int wid  = tid >> 5;
    const int wm   = (wid & 3) * 32;        // warp M offset
    const int wn   = (wid >> 2) * 64;       // warp N offset

    int z = blockIdx.z;
    int zb = z / Hdiv, zh = z - zb * Hdiv;
    const long long offA = zb * sAb + zh * sAz;
    const long long offB = zb * sBb + zh * sBz;
    A  += offA;
    Bm += offB;
    if (DUAL) { A2 += offA; B2 += offB; }
    const long long offC = zb * sCb + zh * sCz;
    if (OM == OM_F32) C += offC; else Ch += offC;

    // staging: each tile 128 rows x 32 k fp16 = 8KB; 256 thr x 2 cp16 each
    const int arow = tid >> 1;
    const int aseg = (tid & 1) * 16;            // fp16 elems (32B per thread)
    const long long aoff = (long long)(blockIdx.y * 128 + arow) * lda + aseg;
    const long long boff = (long long)(blockIdx.x * 128 + arow) * ldb + aseg;
    const uint32_t dstA = smb + arow * PITCH + aseg * 2;
    const uint32_t dstB = smb + OF_B + arow * PITCH + aseg * 2;

    float acc[2][8][4];
#pragma unroll
    for (int i = 0; i < 2; i++)
#pragma unroll
        for (int j = 0; j < 8; j++)
#pragma unroll
            for (int k = 0; k < 4; k++) acc[i][j][k] = 0.f;

    const int nch   = K >> 5;
    const int total = DUAL ? nch * 2 : nch;

    auto issue = [&](int c) {
        const __half *a = A, *b = Bm;
        int cc = c;
        if (DUAL && c >= nch) { a = A2; b = B2; cc = c - nch; }
        const long long ka = aoff + cc * 32;
        const long long kb = boff + cc * 32;
        const uint32_t stg = (c & (NSTAGE - 1)) * STAGE_SZ;
        cp16(dstA + stg,      a + ka);
        cp16(dstA + stg + 16, a + ka + 8);
        cp16(dstB + stg,      b + kb);
        cp16(dstB + stg + 16, b + kb + 8);
    };

    auto COMPUTE = [&](int s) {
        const uint32_t sa = smb + s * STAGE_SZ;
#pragma unroll
        for (int ks = 0; ks < 2; ++ks) {
            const uint32_t colb = ks * 32;
            uint32_t af[2][4];
#pragma unroll
            for (int mt = 0; mt < 2; ++mt) {
                uint32_t addr = sa +
                    (wm + mt * 16 + (lane & 15)) * PITCH + colb + (lane >> 4) * 16;
                ldm_x4(addr, af[mt]);
            }
#pragma unroll
            for (int np = 0; np < 4; ++np) {
                uint32_t bf[4];
                uint32_t addr = sa + OF_B +
                    (wn + np * 16 + (lane & 7) + ((lane >> 4) << 3)) * PITCH +
                    colb + ((lane >> 3) & 1) * 16;
                ldm_x4(addr, bf);
#pragma unroll
                for (int mt = 0; mt < 2; ++mt)
#pragma unroll
                    for (int ntl = 0; ntl < 2; ++ntl)
                        mma_h(acc[mt][np * 2 + ntl], af[mt],
                              bf[2 * ntl], bf[2 * ntl + 1]);
            }
        }
    };

    // 2-stage pipeline, one sync per chunk
    issue(0); CP_COMMIT;
    for (int c = 0; c < total; ++c) {
        if (c + 1 < total) { issue(c + 1); CP_COMMIT; CP_WAIT1; } else { CP_WAIT0; }
        __syncthreads();
        COMPUTE(c & (NSTAGE - 1));
        __syncthreads();
    }

    // epilogue
    const int g = lane >> 2, t = lane & 3;
#pragma unroll
    for (int mt = 0; mt < 2; ++mt) {
        const int r0 = blockIdx.y * 128 + wm + mt * 16 + g;
#pragma unroll
        for (int nt = 0; nt < 8; ++nt) {
            const int col = blockIdx.x * 128 + wn + nt * 8 + t * 2;
            float b0 = 0.f, b1 = 0.f;
            if (BIAS) { b0 = bias[col]; b1 = bias[col + 1]; }
            float2 v0, v1;
            v0.x = alpha * acc[mt][nt][0] + b0;
            v0.y = alpha * acc[mt][nt][1] + b1;
            v1.x = alpha * acc[mt][nt][2] + b0;
            v1.y = alpha * acc[mt][nt][3] + b1;
            if (OM == OM_F32) {
                *(float2*)&C[(long long)r0 * ldc + col] = v0;
                *(float2*)&C[(long long)(r0 + 8) * ldc + col] = v1;
            } else {
                *(uint32_t*)&Ch[(long long)r0 * ldc + col] = packh(v0.x, v0.y);
                *(uint32_t*)&Ch[(long long)(r0 + 8) * ldc + col] = packh(v1.x, v1.y);
            }
        }
    }
}

// ---------------------------------------------------------------------------
// Convert fp32 -> plain fp16, 9 jobs in one launch (grid.y selects job)
// ---------------------------------------------------------------------------
struct ConvJob  { const float* s; __half* h; int n4; };
struct ConvJobs { ConvJob j[9]; };

__global__ void conv_all(ConvJobs js)
{
    ConvJob job = js.j[blockIdx.y];
    int i = blockIdx.x * blockDim.x + threadIdx.x;
    if (i >= job.n4) return;
    float4 v = ((const float4*)job.s)[i];
    uint32_t h0 = packh(v.x, v.y), h1 = packh(v.z, v.w);
    ((uint2*)job.h)[i] = make_uint2(h0, h1);
}

// ---------------------------------------------------------------------------
// RoPE: read fp32, rotate, write plain fp16
// ---------------------------------------------------------------------------
__global__ void rope_conv(const float* __restrict__ src,
                          __half* __restrict__ dst,
                          const float* __restrict__ fc,
                          const float* __restrict__ fs)
{
    long long idx = (long long)blockIdx.x * blockDim.x + threadIdx.x;
    const long long total = (long long)MR * NH * (DH / 2);
    if (idx >= total) return;
    int i = (int)(idx & 63);
    long long t2 = idx >> 6;
    int h = (int)(t2 % NH);
    long long row = t2 / NH;
    int s = (int)(row % SS);
    float c  = fc[s * 64 + i];
    float sn = fs[s * 64 + i];
    size_t off = (size_t)row * HD + h * DH + 2 * i;
    float e = src[off], o = src[off + 1];
    *(uint32_t*)&dst[off] = packh(e * c - o * sn, e * sn + o * c);
}

// ---------------------------------------------------------------------------
// Transpose V -> plain fp16: vt[z*DH + d][s] = v[(b*SS+s)*HD + h*DH + d]
// ---------------------------------------------------------------------------
__global__ void transpose_half(const float* __restrict__ v,
                               __half* __restrict__ vt)
{
    __shared__ float t[32][33];
    int z = blockIdx.z;
    int b = z / NH, h = z - b * NH;
    int s0 = blockIdx.y * 32, d0 = blockIdx.x * 32;
    int x = threadIdx.x, y = threadIdx.y;
#pragma unroll
    for (int i = 0; i < 32; i += 8)
        t[y + i][x] = v[((long long)(b * SS + s0 + y + i)) * HD + h * DH + d0 + x];
    __syncthreads();
#pragma unroll
    for (int i = 0; i < 32; i += 8) {
        size_t off = ((size_t)(z * DH + d0 + y + i)) * SS + s0 + x;
        vt[off] = __float2half_rn(t[x][y + i]);
    }
}

// ---------------------------------------------------------------------------
// Softmax: fp32 row (2048) -> normalized P as plain fp16
// ---------------------------------------------------------------------------
__global__ __launch_bounds__(256) void softmax_conv(const float* __restrict__ S,
                                                    __half* __restrict__ Ph)
{
    const float* p = S + (long long)blockIdx.x * SS;
    uint32_t* oh = (uint32_t*)(Ph + (long long)blockIdx.x * SS);
    const int t = threadIdx.x;
    __shared__ float red[8];

    float2 v[4];
#pragma unroll
    for (int j = 0; j < 4; ++j) v[j] = *(const float2*)&p[2 * t + 512 * j];

    float m = fmaxf(v[0].x, v[0].y);
#pragma unroll
    for (int j = 1; j < 4; ++j) m = fmaxf(m, fmaxf(v[j].x, v[j].y));
#pragma unroll
    for (int o = 16; o > 0; o >>= 1) m = fmaxf(m, __shfl_xor_sync(~0u, m, o));
    if ((t & 31) == 0) red[t >> 5] = m;
    __syncthreads();
    if (t < 32) {
        float mm = red[t & 7];
#pragma unroll
        for (int o = 4; o > 0; o >>= 1) mm = fmaxf(mm, __shfl_xor_sync(~0u, mm, o));
        if (t == 0) red[0] = mm;
    }
    __syncthreads();
    m = red[0];
    __syncthreads();

    float sum = 0.f;
#pragma unroll
    for (int j = 0; j < 4; ++j) {
        v[j].x = __expf(v[j].x - m);
        v[j].y = __expf(v[j].y - m);
        sum += v[j].x + v[j].y;
    }
#pragma unroll
    for (int o = 16; o > 0; o >>= 1) sum += __shfl_xor_sync(~0u, sum, o);
    if ((t & 31) == 0) red[t >> 5] = sum;
    __syncthreads();
    if (t < 32) {
        float ss = red[t & 7];
#pragma unroll
        for (int o = 4; o > 0; o >>= 1) ss += __shfl_xor_sync(~0u, ss, o);
        if (t == 0) red[0] = ss;
    }
    __syncthreads();
    const float inv = 1.0f / red[0];
#pragma unroll
    for (int j = 0; j < 4; ++j)
        oh[t + 256 * j] = packh(v[j].x * inv, v[j].y * inv);
}

// ---------------------------------------------------------------------------

extern "C" void kernel_launch(void* const* d_in, const int* in_sizes, int n_in,
                              void* d_out, int out_size)
{
    const float* x    = (const float*)d_in[0];
    const float* fc   = (const float*)d_in[1];
    const float* fs   = (const float*)d_in[2];
    const float* w_lq = (const float*)d_in[3];
    const float* w_lkv= (const float*)d_in[4];
    const float* w_q  = (const float*)d_in[5];
    const float* w_k  = (const float*)d_in[6];
    const float* w_v  = (const float*)d_in[7];
    const float* w_qr = (const float*)d_in[8];
    const float* b_qr = (const float*)d_in[9];
    const float* w_kr = (const float*)d_in[10];
    const float* b_kr = (const float*)d_in[11];
    const float* w_o  = (const float*)d_in[12];
    const float* b_o  = (const float*)d_in[13];
    float* out = (float*)d_out;

    float *qr, *kr, *vv, *sc;
    cudaGetSymbolAddress((void**)&qr, g_qr);
    cudaGetSymbolAddress((void**)&kr, g_kr);
    cudaGetSymbolAddress((void**)&vv, g_v);
    cudaGetSymbolAddress((void**)&sc, g_sc);

    __half *xh, *cq, *ckv, *qa, *qrs, *ka, *krs, *vt, *pp, *att;
    __half *wlq, *wlkv, *wq, *wqr, *wk, *wv, *wkr, *wo;
    cudaGetSymbolAddress((void**)&xh,   g_x);
    cudaGetSymbolAddress((void**)&cq,   g_cq);
    cudaGetSymbolAddress((void**)&ckv,  g_ckv);
    cudaGetSymbolAddress((void**)&qa,   g_qa);
    cudaGetSymbolAddress((void**)&qrs,  g_qrs);
    cudaGetSymbolAddress((void**)&ka,   g_ka);
    cudaGetSymbolAddress((void**)&krs,  g_krs);
    cudaGetSymbolAddress((void**)&vt,   g_vt);
    cudaGetSymbolAddress((void**)&pp,   g_p);
    cudaGetSymbolAddress((void**)&att,  g_att);
    cudaGetSymbolAddress((void**)&wlq,  g_wlq);
    cudaGetSymbolAddress((void**)&wlkv, g_wlkv);
    cudaGetSymbolAddress((void**)&wq,   g_wq);
    cudaGetSymbolAddress((void**)&wqr,  g_wqr);
    cudaGetSymbolAddress((void**)&wk,   g_wk);
    cudaGetSymbolAddress((void**)&wv,   g_wv);
    cudaGetSymbolAddress((void**)&wkr,  g_wkr);
    cudaGetSymbolAddress((void**)&wo,   g_wo);

    cudaFuncSetAttribute(bgemm<OM_HALF, false, false>, cudaFuncAttributeMaxDynamicSharedMemorySize, SMEMSZ);
    cudaFuncSetAttribute(bgemm<OM_F32,  true,  false>, cudaFuncAttributeMaxDynamicSharedMemorySize, SMEMSZ);
    cudaFuncSetAttribute(bgemm<OM_F32,  false, false>, cudaFuncAttributeMaxDynamicSharedMemorySize, SMEMSZ);
    cudaFuncSetAttribute(bgemm<OM_F32,  false, true >, cudaFuncAttributeMaxDynamicSharedMemorySize, SMEMSZ);

    const float scale = 0.08838834764831845f; // 1/sqrt(128)

    // --- convert x + all weights to plain fp16 ---
    {
        ConvJobs js;
        js.j[0] = { x,     xh,   MR*DIM/4 };
        js.j[1] = { w_lq,  wlq,  LQ*DIM/4 };
        js.j[2] = { w_lkv, wlkv, LKV*DIM/4 };
        js.j[3] = { w_q,   wq,   HD*LQ/4 };
        js.j[4] = { w_qr,  wqr,  HD*LQ/4 };
        js.j[5] = { w_k,   wk,   HD*LKV/4 };
        js.j[6] = { w_v,   wv,   HD*LKV/4 };
        js.j[7] = { w_kr,  wkr,  HD*DIM/4 };
        js.j[8] = { w_o,   wo,   DIM*HD/4 };
        conv_all<<<dim3((MR*DIM/4 + 255)/256, 9), 256>>>(js);
    }

    // --- projections ---
    // cq = x @ w_lq^T -> fp16
    bgemm<OM_HALF, false, false><<<dim3(LQ/128, MR/128, 1), 256, SMEMSZ>>>(
        DIM, xh, DIM, 0, 0, wlq, DIM, 0, 0, nullptr, nullptr,
        nullptr, LQ, 0, 0, nullptr, 1.f, 1, cq);
    // ckv = x @ w_lkv^T -> fp16
    bgemm<OM_HALF, false, false><<<dim3(LKV/128, MR/128, 1), 256, SMEMSZ>>>(
        DIM, xh, DIM, 0, 0, wlkv, DIM, 0, 0, nullptr, nullptr,
        nullptr, LKV, 0, 0, nullptr, 1.f, 1, ckv);
    // qa = cq @ w_q^T -> fp16
    bgemm<OM_HALF, false, false><<<dim3(HD/128, MR/128, 1), 256, SMEMSZ>>>(
        LQ, cq, LQ, 0, 0, wq, LQ, 0, 0, nullptr, nullptr,
        nullptr, HD, 0, 0, nullptr, 1.f, 1, qa);
    // qr = cq @ w_qr^T + b_qr -> fp32 (pre-rope)
    bgemm<OM_F32, true, false><<<dim3(HD/128, MR/128, 1), 256, SMEMSZ>>>(
        LQ, cq, LQ, 0, 0, wqr, LQ, 0, 0, nullptr, nullptr,
        qr, HD, 0, 0, b_qr, 1.f, 1, nullptr);
    // ka = ckv @ w_k^T -> fp16
    bgemm<OM_HALF, false, false><<<dim3(HD/128, MR/128, 1), 256, SMEMSZ>>>(
        LKV, ckv, LKV, 0, 0, wk, LKV, 0, 0, nullptr, nullptr,
        nullptr, HD, 0, 0, nullptr, 1.f, 1, ka);
    // kr = x @ w_kr^T + b_kr -> fp32 (pre-rope)
    bgemm<OM_F32, true, false><<<dim3(HD/128, MR/128, 1), 256, SMEMSZ>>>(
        DIM, xh, DIM, 0, 0, wkr, DIM, 0, 0, nullptr, nullptr,
        kr, HD, 0, 0, b_kr, 1.f, 1, nullptr);
    // v = ckv @ w_v^T -> fp32 (pre-transpose)
    bgemm<OM_F32, false, false><<<dim3(HD/128, MR/128, 1), 256, SMEMSZ>>>(
        LKV, ckv, LKV, 0, 0, wv, LKV, 0, 0, nullptr, nullptr,
        vv, HD, 0, 0, nullptr, 1.f, 1, nullptr);

    // --- RoPE: qr, kr -> plain fp16 ---
    {
        long long pairs = (long long)MR * NH * (DH / 2);
        int blocks = (int)((pairs + 255) / 256);
        rope_conv<<<blocks, 256>>>(qr, qrs, fc, fs);
        rope_conv<<<blocks, 256>>>(kr, krs, fc, fs);
    }

    // --- transpose V -> plain fp16 ---
    transpose_half<<<dim3(DH/32, SS/32, BB*NH), dim3(32, 8)>>>(vv, vt);

    // --- scores: sc[z] = (qa.ka^T + qr.kr^T) * scale ---
    {
        long long sQb = (long long)SS * HD;
        long long sQz = DH;
        long long sSb = (long long)NH * SS * SS;
        long long sSz = (long long)SS * SS;
        bgemm<OM_F32, false, true><<<dim3(SS/128, SS/128, BB*NH), 256, SMEMSZ>>>(
            DH, qa, HD, sQb, sQz, ka, HD, sQb, sQz, qrs, krs,
            sc, SS, sSb, sSz, nullptr, scale, NH, nullptr);
    }

    // --- softmax -> P plain fp16 ---
    softmax_conv<<<BB * NH * SS, 256>>>(sc, pp);

    // --- PV: att = P @ vt^T -> fp16 ---
    {
        long long sPb = (long long)NH * SS * SS;
        long long sPz = (long long)SS * SS;
        long long sVb = (long long)NH * DH * SS;
        long long sVz = (long long)DH * SS;
        long long sCb = (long long)SS * HD;
        long long sCz = DH;
        bgemm<OM_HALF, false, false><<<dim3(DH/128, SS/128, BB*NH), 256, SMEMSZ>>>(
            SS, pp, SS, sPb, sPz, vt, SS, sVb, sVz, nullptr, nullptr,
            nullptr, HD, sCb, sCz, nullptr, 1.f, NH, att);
    }

    // --- out = att @ w_o^T + b_o ---
    bgemm<OM_F32, true, false><<<dim3(DIM/128, MR/128, 1), 256, SMEMSZ>>>(
        HD, att, HD, 0, 0, wo, HD, 0, 0, nullptr, nullptr,
        out, DIM, 0, 0, b_o, 1.f, 1, nullptr);

    (void)in_sizes; (void)n_in; (void)out_size;
}

// round 17
// speedup vs baseline: 1.5384x; 1.5384x over previous
#include <cuda_runtime.h>
#include <cuda_fp16.h>
#include <cstdint>

// Problem constants
#define BB   2
#define SS   2048
#define DIM  2048
#define NH   16
#define DH   128
#define LKV  512
#define LQ   1024
#define MR   (BB*SS)    // 4096
#define HD   (NH*DH)    // 2048

// fp32 scratch
__device__ float g_qr [MR*(size_t)HD];
__device__ float g_kr [MR*(size_t)HD];
__device__ float g_v  [MR*(size_t)HD];
__device__ float g_sc [(size_t)BB*NH*SS*SS];   // 512 MB scores

// plain fp16 operands
__device__ __half g_x   [MR*(size_t)DIM];
__device__ __half g_cq  [MR*(size_t)LQ];
__device__ __half g_ckv [MR*(size_t)LKV];
__device__ __half g_qa  [MR*(size_t)HD];
__device__ __half g_qrs [MR*(size_t)HD];
__device__ __half g_ka  [MR*(size_t)HD];
__device__ __half g_krs [MR*(size_t)HD];
__device__ __half g_vt  [(size_t)BB*NH*DH*SS];
__device__ __half g_p   [(size_t)BB*NH*SS*SS];
__device__ __half g_att [MR*(size_t)HD];
__device__ __half g_wlq [(size_t)LQ*DIM];
__device__ __half g_wlkv[(size_t)LKV*DIM];
__device__ __half g_wq  [(size_t)HD*LQ];
__device__ __half g_wqr [(size_t)HD*LQ];
__device__ __half g_wk  [(size_t)HD*LKV];
__device__ __half g_wv  [(size_t)HD*LKV];
__device__ __half g_wkr [(size_t)HD*DIM];
__device__ __half g_wo  [(size_t)DIM*HD];

// ---------------------------------------------------------------------------
// Helpers
// ---------------------------------------------------------------------------
__device__ __forceinline__ uint32_t smem_u32(const void* p) {
    uint32_t a;
    asm("{ .reg .u64 t; cvta.to.shared.u64 t, %1; cvt.u32.u64 %0, t; }" : "=r"(a) : "l"(p));
    return a;
}
__device__ __forceinline__ void ldm_x4(uint32_t addr, uint32_t r[4]) {
    asm volatile("ldmatrix.sync.aligned.m8n8.x4.shared.b16 {%0,%1,%2,%3}, [%4];"
                 : "=r"(r[0]), "=r"(r[1]), "=r"(r[2]), "=r"(r[3]) : "r"(addr));
}
__device__ __forceinline__ void mma_h(float c[4], const uint32_t a[4],
                                      uint32_t b0, uint32_t b1) {
    asm volatile(
        "mma.sync.aligned.m16n8k16.row.col.f32.f16.f16.f32 "
        "{%0,%1,%2,%3}, {%4,%5,%6,%7}, {%8,%9}, {%0,%1,%2,%3};"
        : "+f"(c[0]), "+f"(c[1]), "+f"(c[2]), "+f"(c[3])
        : "r"(a[0]), "r"(a[1]), "r"(a[2]), "r"(a[3]), "r"(b0), "r"(b1));
}
__device__ __forceinline__ uint32_t packh(float a, float b) {
    __half2 h = __floats2half2_rn(a, b);
    return *(uint32_t*)&h;
}

__device__ __forceinline__ void cp16(uint32_t dst, const void* src) {
    asm volatile("cp.async.cg.shared.global [%0], [%1], 16;" :: "r"(dst), "l"(src) : "memory");
}
#define CP_COMMIT asm volatile("cp.async.commit_group;" ::: "memory")
#define CP_WAIT0  asm volatile("cp.async.wait_group 0;" ::: "memory")
#define CP_WAIT1  asm volatile("cp.async.wait_group 1;" ::: "memory")

// SMEM per stage: A, B tiles [128 rows x 64 k fp16], pitch 144B (128B data).
// 144 = 16*9: 16B-aligned for ldmatrix, rotates bank phase 16B/row -> no conflicts.
#define PITCH    144
#define OF_B     18432
#define STAGE_SZ 36864
#define NSTAGE   3
#define SMEMSZ   (NSTAGE*STAGE_SZ)     // 110592 -> 2 CTAs/SM (221KB of 228KB)

// Epilogue modes
#define OM_F32   0
#define OM_HALF  1

// ---------------------------------------------------------------------------
// bgemm: C = alpha * A * B^T [+ bias], plain fp16 operands, single MMA.
//   CTA tile 128x128, 256 threads = 8 warps (4M x 2N, warp 32x64).
//   K-chunk 64, 3-stage cp.async pipeline with prefetch distance 2,
//   ONE __syncthreads per chunk. DUAL: continue with A2*B2^T.
//   Batched via grid.z. Grid (N/128, M/128, Z). K multiple of 64.
// ---------------------------------------------------------------------------
template<int OM, bool BIAS, bool DUAL>
__global__ __launch_bounds__(256, 2)
void bgemm(int K,
           const __half* __restrict__ A, int lda, long long sAb, long long sAz,
           const __half* __restrict__ Bm, int ldb, long long sBb, long long sBz,
           const __half* __restrict__ A2, const __half* __restrict__ B2,
           float* __restrict__ C, int ldc, long long sCb, long long sCz,
           const float* __restrict__ bias, float alpha, int Hdiv,
           __half* __restrict__ Ch)
{
    extern __shared__ __align__(128) char smc[];
    const uint32_t smb = smem_u32(smc);
    const int tid  = threadIdx.x;
    const int lane = tid & 31;
    const int wid  = tid >> 5;
    const int wm   = (wid & 3) * 32;        // warp M offset
    const int wn   = (wid >> 2) * 64;       // warp N offset

    int z = blockIdx.z;
    int zb = z / Hdiv, zh = z - zb * Hdiv;
    const long long offA = zb * sAb + zh * sAz;
    const long long offB = zb * sBb + zh * sBz;
    A  += offA;
    Bm += offB;
    if (DUAL) { A2 += offA; B2 += offB; }
    const long long offC = zb * sCb + zh * sCz;
    if (OM == OM_F32) C += offC; else Ch += offC;

    // staging: each tile 128 rows x 64 k fp16 = 16KB data; 2 thr/row, 64B each
    const int arow = tid >> 1;
    const int aseg = (tid & 1) * 32;            // fp16 elems (64B per thread)
    const long long aoff = (long long)(blockIdx.y * 128 + arow) * lda + aseg;
    const long long boff = (long long)(blockIdx.x * 128 + arow) * ldb + aseg;
    const uint32_t dstA = smb + arow * PITCH + aseg * 2;
    const uint32_t dstB = smb + OF_B + arow * PITCH + aseg * 2;

    float acc[2][8][4];
#pragma unroll
    for (int i = 0; i < 2; i++)
#pragma unroll
        for (int j = 0; j < 8; j++)
#pragma unroll
            for (int k = 0; k < 4; k++) acc[i][j][k] = 0.f;

    const int nch   = K >> 6;               // chunks of 64
    const int total = DUAL ? nch * 2 : nch;

    auto issue = [&](int c) {
        const __half *a = A, *b = Bm;
        int cc = c;
        if (DUAL && c >= nch) { a = A2; b = B2; cc = c - nch; }
        const long long ka = aoff + cc * 64;
        const long long kb = boff + cc * 64;
        const uint32_t stg = (c % NSTAGE) * STAGE_SZ;
#pragma unroll
        for (int j = 0; j < 4; ++j) {
            cp16(dstA + stg + 16 * j, a + ka + 8 * j);
            cp16(dstB + stg + 16 * j, b + kb + 8 * j);
        }
    };

    auto COMPUTE = [&](int s) {
        const uint32_t sa = smb + s * STAGE_SZ;
#pragma unroll
        for (int ks = 0; ks < 4; ++ks) {
            const uint32_t colb = ks * 32;
            uint32_t af[2][4];
#pragma unroll
            for (int mt = 0; mt < 2; ++mt) {
                uint32_t addr = sa +
                    (wm + mt * 16 + (lane & 15)) * PITCH + colb + (lane >> 4) * 16;
                ldm_x4(addr, af[mt]);
            }
#pragma unroll
            for (int np = 0; np < 4; ++np) {
                uint32_t bf[4];
                uint32_t addr = sa + OF_B +
                    (wn + np * 16 + (lane & 7) + ((lane >> 4) << 3)) * PITCH +
                    colb + ((lane >> 3) & 1) * 16;
                ldm_x4(addr, bf);
#pragma unroll
                for (int mt = 0; mt < 2; ++mt)
#pragma unroll
                    for (int ntl = 0; ntl < 2; ++ntl)
                        mma_h(acc[mt][np * 2 + ntl], af[mt],
                              bf[2 * ntl], bf[2 * ntl + 1]);
            }
        }
    };

    // 3-stage pipeline, prefetch distance 2, ONE sync per chunk
    issue(0); CP_COMMIT;
    if (total > 1) { issue(1); CP_COMMIT; }
    for (int c = 0; c < total; ++c) {
        if (c + 1 < total) { CP_WAIT1; } else { CP_WAIT0; }
        __syncthreads();
        COMPUTE(c % NSTAGE);
        if (c + 2 < total) { issue(c + 2); CP_COMMIT; }
    }

    // epilogue
    const int g = lane >> 2, t = lane & 3;
#pragma unroll
    for (int mt = 0; mt < 2; ++mt) {
        const int r0 = blockIdx.y * 128 + wm + mt * 16 + g;
#pragma unroll
        for (int nt = 0; nt < 8; ++nt) {
            const int col = blockIdx.x * 128 + wn + nt * 8 + t * 2;
            float b0 = 0.f, b1 = 0.f;
            if (BIAS) { b0 = bias[col]; b1 = bias[col + 1]; }
            float2 v0, v1;
            v0.x = alpha * acc[mt][nt][0] + b0;
            v0.y = alpha * acc[mt][nt][1] + b1;
            v1.x = alpha * acc[mt][nt][2] + b0;
            v1.y = alpha * acc[mt][nt][3] + b1;
            if (OM == OM_F32) {
                *(float2*)&C[(long long)r0 * ldc + col] = v0;
                *(float2*)&C[(long long)(r0 + 8) * ldc + col] = v1;
            } else {
                *(uint32_t*)&Ch[(long long)r0 * ldc + col] = packh(v0.x, v0.y);
                *(uint32_t*)&Ch[(long long)(r0 + 8) * ldc + col] = packh(v1.x, v1.y);
            }
        }
    }
}

// ---------------------------------------------------------------------------
// Convert fp32 -> plain fp16, 9 jobs in one launch (grid.y selects job)
// ---------------------------------------------------------------------------
struct ConvJob  { const float* s; __half* h; int n4; };
struct ConvJobs { ConvJob j[9]; };

__global__ void conv_all(ConvJobs js)
{
    ConvJob job = js.j[blockIdx.y];
    int i = blockIdx.x * blockDim.x + threadIdx.x;
    if (i >= job.n4) return;
    float4 v = ((const float4*)job.s)[i];
    uint32_t h0 = packh(v.x, v.y), h1 = packh(v.z, v.w);
    ((uint2*)job.h)[i] = make_uint2(h0, h1);
}

// ---------------------------------------------------------------------------
// RoPE: read fp32, rotate, write plain fp16
// ---------------------------------------------------------------------------
__global__ void rope_conv(const float* __restrict__ src,
                          __half* __restrict__ dst,
                          const float* __restrict__ fc,
                          const float* __restrict__ fs)
{
    long long idx = (long long)blockIdx.x * blockDim.x + threadIdx.x;
    const long long total = (long long)MR * NH * (DH / 2);
    if (idx >= total) return;
    int i = (int)(idx & 63);
    long long t2 = idx >> 6;
    int h = (int)(t2 % NH);
    long long row = t2 / NH;
    int s = (int)(row % SS);
    float c  = fc[s * 64 + i];
    float sn = fs[s * 64 + i];
    size_t off = (size_t)row * HD + h * DH + 2 * i;
    float e = src[off], o = src[off + 1];
    *(uint32_t*)&dst[off] = packh(e * c - o * sn, e * sn + o * c);
}

// ---------------------------------------------------------------------------
// Transpose V -> plain fp16: vt[z*DH + d][s] = v[(b*SS+s)*HD + h*DH + d]
// ---------------------------------------------------------------------------
__global__ void transpose_half(const float* __restrict__ v,
                               __half* __restrict__ vt)
{
    __shared__ float t[32][33];
    int z = blockIdx.z;
    int b = z / NH, h = z - b * NH;
    int s0 = blockIdx.y * 32, d0 = blockIdx.x * 32;
    int x = threadIdx.x, y = threadIdx.y;
#pragma unroll
    for (int i = 0; i < 32; i += 8)
        t[y + i][x] = v[((long long)(b * SS + s0 + y + i)) * HD + h * DH + d0 + x];
    __syncthreads();
#pragma unroll
    for (int i = 0; i < 32; i += 8) {
        size_t off = ((size_t)(z * DH + d0 + y + i)) * SS + s0 + x;
        vt[off] = __float2half_rn(t[x][y + i]);
    }
}

// ---------------------------------------------------------------------------
// Softmax: fp32 row (2048) -> normalized P as plain fp16
// ---------------------------------------------------------------------------
__global__ __launch_bounds__(256) void softmax_conv(const float* __restrict__ S,
                                                    __half* __restrict__ Ph)
{
    const float* p = S + (long long)blockIdx.x * SS;
    uint32_t* oh = (uint32_t*)(Ph + (long long)blockIdx.x * SS);
    const int t = threadIdx.x;
    __shared__ float red[8];

    float2 v[4];
#pragma unroll
    for (int j = 0; j < 4; ++j) v[j] = *(const float2*)&p[2 * t + 512 * j];

    float m = fmaxf(v[0].x, v[0].y);
#pragma unroll
    for (int j = 1; j < 4; ++j) m = fmaxf(m, fmaxf(v[j].x, v[j].y));
#pragma unroll
    for (int o = 16; o > 0; o >>= 1) m = fmaxf(m, __shfl_xor_sync(~0u, m, o));
    if ((t & 31) == 0) red[t >> 5] = m;
    __syncthreads();
    if (t < 32) {
        float mm = red[t & 7];
#pragma unroll
        for (int o = 4; o > 0; o >>= 1) mm = fmaxf(mm, __shfl_xor_sync(~0u, mm, o));
        if (t == 0) red[0] = mm;
    }
    __syncthreads();
    m = red[0];
    __syncthreads();

    float sum = 0.f;
#pragma unroll
    for (int j = 0; j < 4; ++j) {
        v[j].x = __expf(v[j].x - m);
        v[j].y = __expf(v[j].y - m);
        sum += v[j].x + v[j].y;
    }
#pragma unroll
    for (int o = 16; o > 0; o >>= 1) sum += __shfl_xor_sync(~0u, sum, o);
    if ((t & 31) == 0) red[t >> 5] = sum;
    __syncthreads();
    if (t < 32) {
        float ss = red[t & 7];
#pragma unroll
        for (int o = 4; o > 0; o >>= 1) ss += __shfl_xor_sync(~0u, ss, o);
        if (t == 0) red[0] = ss;
    }
    __syncthreads();
    const float inv = 1.0f / red[0];
#pragma unroll
    for (int j = 0; j < 4; ++j)
        oh[t + 256 * j] = packh(v[j].x * inv, v[j].y * inv);
}

// ---------------------------------------------------------------------------

extern "C" void kernel_launch(void* const* d_in, const int* in_sizes, int n_in,
                              void* d_out, int out_size)
{
    const float* x    = (const float*)d_in[0];
    const float* fc   = (const float*)d_in[1];
    const float* fs   = (const float*)d_in[2];
    const float* w_lq = (const float*)d_in[3];
    const float* w_lkv= (const float*)d_in[4];
    const float* w_q  = (const float*)d_in[5];
    const float* w_k  = (const float*)d_in[6];
    const float* w_v  = (const float*)d_in[7];
    const float* w_qr = (const float*)d_in[8];
    const float* b_qr = (const float*)d_in[9];
    const float* w_kr = (const float*)d_in[10];
    const float* b_kr = (const float*)d_in[11];
    const float* w_o  = (const float*)d_in[12];
    const float* b_o  = (const float*)d_in[13];
    float* out = (float*)d_out;

    float *qr, *kr, *vv, *sc;
    cudaGetSymbolAddress((void**)&qr, g_qr);
    cudaGetSymbolAddress((void**)&kr, g_kr);
    cudaGetSymbolAddress((void**)&vv, g_v);
    cudaGetSymbolAddress((void**)&sc, g_sc);

    __half *xh, *cq, *ckv, *qa, *qrs, *ka, *krs, *vt, *pp, *att;
    __half *wlq, *wlkv, *wq, *wqr, *wk, *wv, *wkr, *wo;
    cudaGetSymbolAddress((void**)&xh,   g_x);
    cudaGetSymbolAddress((void**)&cq,   g_cq);
    cudaGetSymbolAddress((void**)&ckv,  g_ckv);
    cudaGetSymbolAddress((void**)&qa,   g_qa);
    cudaGetSymbolAddress((void**)&qrs,  g_qrs);
    cudaGetSymbolAddress((void**)&ka,   g_ka);
    cudaGetSymbolAddress((void**)&krs,  g_krs);
    cudaGetSymbolAddress((void**)&vt,   g_vt);
    cudaGetSymbolAddress((void**)&pp,   g_p);
    cudaGetSymbolAddress((void**)&att,  g_att);
    cudaGetSymbolAddress((void**)&wlq,  g_wlq);
    cudaGetSymbolAddress((void**)&wlkv, g_wlkv);
    cudaGetSymbolAddress((void**)&wq,   g_wq);
    cudaGetSymbolAddress((void**)&wqr,  g_wqr);
    cudaGetSymbolAddress((void**)&wk,   g_wk);
    cudaGetSymbolAddress((void**)&wv,   g_wv);
    cudaGetSymbolAddress((void**)&wkr,  g_wkr);
    cudaGetSymbolAddress((void**)&wo,   g_wo);

    cudaFuncSetAttribute(bgemm<OM_HALF, false, false>, cudaFuncAttributeMaxDynamicSharedMemorySize, SMEMSZ);
    cudaFuncSetAttribute(bgemm<OM_F32,  true,  false>, cudaFuncAttributeMaxDynamicSharedMemorySize, SMEMSZ);
    cudaFuncSetAttribute(bgemm<OM_F32,  false, false>, cudaFuncAttributeMaxDynamicSharedMemorySize, SMEMSZ);
    cudaFuncSetAttribute(bgemm<OM_F32,  false, true >, cudaFuncAttributeMaxDynamicSharedMemorySize, SMEMSZ);

    const float scale = 0.08838834764831845f; // 1/sqrt(128)

    // --- convert x + all weights to plain fp16 ---
    {
        ConvJobs js;
        js.j[0] = { x,     xh,   MR*DIM/4 };
        js.j[1] = { w_lq,  wlq,  LQ*DIM/4 };
        js.j[2] = { w_lkv, wlkv, LKV*DIM/4 };
        js.j[3] = { w_q,   wq,   HD*LQ/4 };
        js.j[4] = { w_qr,  wqr,  HD*LQ/4 };
        js.j[5] = { w_k,   wk,   HD*LKV/4 };
        js.j[6] = { w_v,   wv,   HD*LKV/4 };
        js.j[7] = { w_kr,  wkr,  HD*DIM/4 };
        js.j[8] = { w_o,   wo,   DIM*HD/4 };
        conv_all<<<dim3((MR*DIM/4 + 255)/256, 9), 256>>>(js);
    }

    // --- projections ---
    bgemm<OM_HALF, false, false><<<dim3(LQ/128, MR/128, 1), 256, SMEMSZ>>>(
        DIM, xh, DIM, 0, 0, wlq, DIM, 0, 0, nullptr, nullptr,
        nullptr, LQ, 0, 0, nullptr, 1.f, 1, cq);
    bgemm<OM_HALF, false, false><<<dim3(LKV/128, MR/128, 1), 256, SMEMSZ>>>(
        DIM, xh, DIM, 0, 0, wlkv, DIM, 0, 0, nullptr, nullptr,
        nullptr, LKV, 0, 0, nullptr, 1.f, 1, ckv);
    bgemm<OM_HALF, false, false><<<dim3(HD/128, MR/128, 1), 256, SMEMSZ>>>(
        LQ, cq, LQ, 0, 0, wq, LQ, 0, 0, nullptr, nullptr,
        nullptr, HD, 0, 0, nullptr, 1.f, 1, qa);
    bgemm<OM_F32, true, false><<<dim3(HD/128, MR/128, 1), 256, SMEMSZ>>>(
        LQ, cq, LQ, 0, 0, wqr, LQ, 0, 0, nullptr, nullptr,
        qr, HD, 0, 0, b_qr, 1.f, 1, nullptr);
    bgemm<OM_HALF, false, false><<<dim3(HD/128, MR/128, 1), 256, SMEMSZ>>>(
        LKV, ckv, LKV, 0, 0, wk, LKV, 0, 0, nullptr, nullptr,
        nullptr, HD, 0, 0, nullptr, 1.f, 1, ka);
    bgemm<OM_F32, true, false><<<dim3(HD/128, MR/128, 1), 256, SMEMSZ>>>(
        DIM, xh, DIM, 0, 0, wkr, DIM, 0, 0, nullptr, nullptr,
        kr, HD, 0, 0, b_kr, 1.f, 1, nullptr);
    bgemm<OM_F32, false, false><<<dim3(HD/128, MR/128, 1), 256, SMEMSZ>>>(
        LKV, ckv, LKV, 0, 0, wv, LKV, 0, 0, nullptr, nullptr,
        vv, HD, 0, 0, nullptr, 1.f, 1, nullptr);

    // --- RoPE: qr, kr -> plain fp16 ---
    {
        long long pairs = (long long)MR * NH * (DH / 2);
        int blocks = (int)((pairs + 255) / 256);
        rope_conv<<<blocks, 256>>>(qr, qrs, fc, fs);
        rope_conv<<<blocks, 256>>>(kr, krs, fc, fs);
    }

    // --- transpose V -> plain fp16 ---
    transpose_half<<<dim3(DH/32, SS/32, BB*NH), dim3(32, 8)>>>(vv, vt);

    // --- scores: sc[z] = (qa.ka^T + qr.kr^T) * scale ---
    {
        long long sQb = (long long)SS * HD;
        long long sQz = DH;
        long long sSb = (long long)NH * SS * SS;
        long long sSz = (long long)SS * SS;
        bgemm<OM_F32, false, true><<<dim3(SS/128, SS/128, BB*NH), 256, SMEMSZ>>>(
            DH, qa, HD, sQb, sQz, ka, HD, sQb, sQz, qrs, krs,
            sc, SS, sSb, sSz, nullptr, scale, NH, nullptr);
    }

    // --- softmax -> P plain fp16 ---
    softmax_conv<<<BB * NH * SS, 256>>>(sc, pp);

    // --- PV: att = P @ vt^T -> fp16 ---
    {
        long long sPb = (long long)NH * SS * SS;
        long long sPz = (long long)SS * SS;
        long long sVb = (long long)NH * DH * SS;
        long long sVz = (long long)DH * SS;
        long long sCb = (long long)SS * HD;
        long long sCz = DH;
        bgemm<OM_HALF, false, false><<<dim3(DH/128, SS/128, BB*NH), 256, SMEMSZ>>>(
            SS, pp, SS, sPb, sPz, vt, SS, sVb, sVz, nullptr, nullptr,
            nullptr, HD, sCb, sCz, nullptr, 1.f, NH, att);
    }

    // --- out = att @ w_o^T + b_o ---
    bgemm<OM_F32, true, false><<<dim3(DIM/128, MR/128, 1), 256, SMEMSZ>>>(
        HD, att, HD, 0, 0, wo, HD, 0, 0, nullptr, nullptr,
        out, DIM, 0, 0, b_o, 1.f, 1, nullptr);

    (void)in_sizes; (void)n_in; (void)out_size;
}